// round 10
// baseline (speedup 1.0000x reference)
#include <cuda_runtime.h>
#include <cuda_fp16.h>
#include <cstdint>

// Problem constants
#define B_    16
#define CIN   256
#define COUT  256
#define EPS_F 1e-8f
#define NT    16384            // Winograd tiles total (16 b * 32 * 32)

// ================= scratch =================
__device__ float g_snorm;
__device__ float g_wsq[COUT*CIN];
__device__ float g_invwn[COUT];
__device__ float g_scale[B_*COUT];
// V: [tap 16][T 16384][ci 256] fp16 (134MB)
__device__ __align__(16) __half g_V[(size_t)16*NT*CIN];
// U: [tap 16][co 256][ci 256] fp16 (2MB)
__device__ __align__(16) __half g_U[16*COUT*CIN];
// M: [tap 16][co 256][T 16384] fp16 (134MB)
__device__ __align__(16) __half g_M[(size_t)16*COUT*NT];

// ================= helpers =================
__device__ __forceinline__ void mma_fp16(float& d0, float& d1, float& d2, float& d3,
                                         uint32_t a0, uint32_t a1, uint32_t a2, uint32_t a3,
                                         uint32_t b0, uint32_t b1) {
    asm volatile("mma.sync.aligned.m16n8k16.row.col.f32.f16.f16.f32 "
                 "{%0,%1,%2,%3}, {%4,%5,%6,%7}, {%8,%9}, {%0,%1,%2,%3};"
                 : "+f"(d0), "+f"(d1), "+f"(d2), "+f"(d3)
                 : "r"(a0), "r"(a1), "r"(a2), "r"(a3), "r"(b0), "r"(b1));
}
__device__ __forceinline__ void cp_async16(uint32_t saddr, const void* gaddr) {
    asm volatile("cp.async.cg.shared.global [%0], [%1], 16;"
                 :: "r"(saddr), "l"(gaddr) : "memory");
}
__device__ __forceinline__ void cp_commit() {
    asm volatile("cp.async.commit_group;" ::: "memory");
}
__device__ __forceinline__ void cp_wait2() {
    asm volatile("cp.async.wait_group 2;" ::: "memory");
}
__device__ __forceinline__ uint32_t smem_u32(const void* p) {
    uint32_t a;
    asm("{ .reg .u64 t; cvta.to.shared.u64 t, %1; cvt.u32.u64 %0, t; }"
        : "=r"(a) : "l"(p));
    return a;
}

// ================= norm/scale kernels =================
__global__ void k_snorm(const float* __restrict__ s) {
    __shared__ float red[256];
    float acc = 0.f;
    for (int i = threadIdx.x; i < B_*CIN; i += 256) { float v = s[i]; acc += v*v; }
    red[threadIdx.x] = acc; __syncthreads();
    for (int off = 128; off > 0; off >>= 1) {
        if (threadIdx.x < off) red[threadIdx.x] += red[threadIdx.x + off];
        __syncthreads();
    }
    if (threadIdx.x == 0) g_snorm = rsqrtf(red[0] / (float)(B_*CIN));
}

// merged: weight stats + Winograd weight transform (single w read)
__global__ void k_wprep(const float* __restrict__ w) {
    __shared__ float red[256];
    int co = blockIdx.x, ci = threadIdx.x;
    const float* gp = w + ((size_t)co*CIN + ci)*9;
    float g0[3], g1[3], g2[3];
#pragma unroll
    for (int c = 0; c < 3; ++c) { g0[c]=gp[c]; g1[c]=gp[3+c]; g2[c]=gp[6+c]; }
    float s9 = 0.f;
#pragma unroll
    for (int c = 0; c < 3; ++c) s9 += g0[c]*g0[c] + g1[c]*g1[c] + g2[c]*g2[c];
    g_wsq[co*CIN + ci] = s9;
    red[ci] = s9; __syncthreads();
    for (int off = 128; off > 0; off >>= 1) {
        if (ci < off) red[ci] += red[ci + off];
        __syncthreads();
    }
    if (ci == 0) g_invwn[co] = rsqrtf(red[0] / (float)(CIN*9));

    float tm[4][3];
#pragma unroll
    for (int c = 0; c < 3; ++c) {
        tm[0][c] = g0[c];
        tm[1][c] = 0.5f*(g0[c] + g1[c] + g2[c]);
        tm[2][c] = 0.5f*(g0[c] - g1[c] + g2[c]);
        tm[3][c] = g2[c];
    }
#pragma unroll
    for (int r = 0; r < 4; ++r) {
        float u0 = tm[r][0];
        float u1 = 0.5f*(tm[r][0] + tm[r][1] + tm[r][2]);
        float u2 = 0.5f*(tm[r][0] - tm[r][1] + tm[r][2]);
        float u3 = tm[r][2];
        g_U[(((size_t)((r*4+0)*COUT + co))<<8) + ci] = __float2half_rn(u0);
        g_U[(((size_t)((r*4+1)*COUT + co))<<8) + ci] = __float2half_rn(u1);
        g_U[(((size_t)((r*4+2)*COUT + co))<<8) + ci] = __float2half_rn(u2);
        g_U[(((size_t)((r*4+3)*COUT + co))<<8) + ci] = __float2half_rn(u3);
    }
}

__global__ void k_scale(const float* __restrict__ s) {
    __shared__ float red[256];
    int co = blockIdx.x, b = blockIdx.y, ci = threadIdx.x;
    float sn = s[b*CIN + ci] * g_snorm;
    red[ci] = sn*sn * g_wsq[co*CIN + ci]; __syncthreads();
    for (int off = 128; off > 0; off >>= 1) {
        if (ci < off) red[ci] += red[ci + off];
        __syncthreads();
    }
    if (ci == 0) {
        float iw = g_invwn[co];
        g_scale[b*COUT + co] = iw * rsqrtf(iw*iw*red[0] + EPS_F);
    }
}

// ================= input transform: V = B^T (x*s*snorm) B =================
// Block covers 8 output rows (4 ty) -> 10 input rows; x re-read 1.25x (was 2x).
// grid (8 tyG, 8 ciT, 16 b), 256 threads; dyn smem [10][32][67] fp32 = 85760B
#define XS_BYTES (10*32*67*4)
__global__ __launch_bounds__(256, 2)
void k_wino_x(const float* __restrict__ x, const float* __restrict__ s) {
    extern __shared__ float smx[];   // (r*32 + ci)*67 + col
    const int tid = threadIdx.x;
    const int tyG = blockIdx.x, ciT = blockIdx.y, b = blockIdx.z;
    const float snorm = g_snorm;
    const int r0 = 8*tyG - 1;
    // load 10 rows x 32 ci x 64 cols = 5120 float4, 20/thread
#pragma unroll
    for (int it = 0; it < 20; ++it) {
        int lin = it*256 + tid;
        int c4 = lin & 15;
        int rest = lin >> 4;          // 0..319
        int r = rest % 10;
        int ci = rest / 10;
        int gci = ciT*32 + ci;
        int gr = r0 + r;
        float4 v = make_float4(0.f, 0.f, 0.f, 0.f);
        if ((unsigned)gr < 64u)
            v = *(const float4*)(x + (((size_t)(b*CIN + gci)) << 12) + gr*64 + c4*4);
        float m = s[b*CIN + gci] * snorm;
        float* d = &smx[(r*32 + ci)*67 + 1 + 4*c4];
        d[0] = v.x*m; d[1] = v.y*m; d[2] = v.z*m; d[3] = v.w*m;
        if (c4 == 0)  smx[(r*32 + ci)*67 + 0]  = 0.f;
        if (c4 == 15) smx[(r*32 + ci)*67 + 65] = 0.f;
    }
    __syncthreads();
    const int ci = tid & 31, txq = tid >> 5;
#pragma unroll
    for (int sub = 0; sub < 4; ++sub) {
        int ty = tyG*4 + sub;
#pragma unroll
        for (int k = 0; k < 4; ++k) {
            int tx = txq + 8*k;
            float d[4][4];
#pragma unroll
            for (int r = 0; r < 4; ++r)
#pragma unroll
                for (int c = 0; c < 4; ++c)
                    d[r][c] = smx[((2*sub + r)*32 + ci)*67 + 2*tx + c];
            float m0[4], m1[4], m2[4], m3[4];
#pragma unroll
            for (int j = 0; j < 4; ++j) {
                m0[j] = d[0][j] - d[2][j];
                m1[j] = d[1][j] + d[2][j];
                m2[j] = d[2][j] - d[1][j];
                m3[j] = d[1][j] - d[3][j];
            }
            float V[4][4];
#pragma unroll
            for (int r = 0; r < 4; ++r) {
                const float* mr = (r==0)?m0:(r==1)?m1:(r==2)?m2:m3;
                V[r][0] = mr[0] - mr[2];
                V[r][1] = mr[1] + mr[2];
                V[r][2] = mr[2] - mr[1];
                V[r][3] = mr[1] - mr[3];
            }
            int T = b*1024 + ty*32 + tx;
#pragma unroll
            for (int r = 0; r < 4; ++r)
#pragma unroll
                for (int c = 0; c < 4; ++c)
                    g_V[(((size_t)((r*4+c)*NT + T)) << 8) + ciT*32 + ci] =
                        __float2half_rn(V[r][c]);
        }
    }
}

// ================= kernel A: batched GEMM  M[tap] = U[tap] x V[tap] ====
// CTA 128co x 128T, warp m32 x n64 (8 warps: wm=wid&3, wn=wid>>2).
// K=256 in 8 phases of 32. 4-stage cp.async, one barrier/phase, 2 CTA/SM.
#define KSTR 40
#define AT_HALFS (128*KSTR)                      // 5120
#define STG_HALFS (2*AT_HALFS)                   // 10240
#define GSMEM_BYTES (4*STG_HALFS*2)              // 81920
#define MSTR 136

__global__ __launch_bounds__(256, 2)
void k_gemm() {
    extern __shared__ __half smem[];
    const uint32_t smem_base = smem_u32(smem);

    const int t    = threadIdx.x;
    const int lane = t & 31;
    const int wm   = (t >> 5) & 3;        // m32 block
    const int wn   = t >> 7;              // n64 block
    const int g    = lane >> 2;
    const int t4   = lane & 3;

    const int coT   = blockIdx.x;         // 0..1 (fastest: shares V slab in L2)
    const int Tbase = blockIdx.y * 128;
    const int tap   = blockIdx.z;

    float c[2][8][4];
#pragma unroll
    for (int mb = 0; mb < 2; ++mb)
#pragma unroll
        for (int nb = 0; nb < 8; ++nb)
#pragma unroll
            for (int q = 0; q < 4; ++q) c[mb][nb][q] = 0.f;

    auto load_phase = [&](int p, int j) {
        uint32_t sbase = smem_base + (j*STG_HALFS)*2;
#pragma unroll
        for (int k2 = 0; k2 < 2; ++k2) {
            int lin = k2*256 + t;
            int row = lin >> 2, q = lin & 3;
            const __half* src = g_U + (((size_t)(tap*COUT + coT*128 + row)) << 8)
                              + p*32 + q*8;
            cp_async16(sbase + (row*KSTR + q*8)*2, src);
        }
#pragma unroll
        for (int k2 = 0; k2 < 2; ++k2) {
            int lin = k2*256 + t;
            int row = lin >> 2, q = lin & 3;
            const __half* src = g_V + (((size_t)(tap*NT + Tbase + row)) << 8)
                              + p*32 + q*8;
            cp_async16(sbase + (AT_HALFS + row*KSTR + q*8)*2, src);
        }
    };

#pragma unroll
    for (int p = 0; p < 3; ++p) { load_phase(p, p); cp_commit(); }

    for (int p = 0; p < 8; ++p) {
        const int j = p & 3;
        cp_wait2();
        __syncthreads();
        if (p + 3 < 8) load_phase(p + 3, (p + 3) & 3);
        cp_commit();

        const __half* A  = smem + j*STG_HALFS;
        const __half* Bm = A + AT_HALFS;
#pragma unroll
        for (int ks = 0; ks < 2; ++ks) {
            uint32_t a[2][4];
#pragma unroll
            for (int mb = 0; mb < 2; ++mb) {
                const __half* ap = A + (wm*32 + mb*16 + g)*KSTR + ks*16 + 2*t4;
                a[mb][0] = *(const uint32_t*)(ap);
                a[mb][1] = *(const uint32_t*)(ap + 8*KSTR);
                a[mb][2] = *(const uint32_t*)(ap + 8);
                a[mb][3] = *(const uint32_t*)(ap + 8*KSTR + 8);
            }
            uint32_t bf[8][2];
#pragma unroll
            for (int nb = 0; nb < 8; ++nb) {
                const __half* bp = Bm + (wn*64 + nb*8 + g)*KSTR + ks*16 + 2*t4;
                bf[nb][0] = *(const uint32_t*)(bp);
                bf[nb][1] = *(const uint32_t*)(bp + 8);
            }
#pragma unroll
            for (int mb = 0; mb < 2; ++mb)
#pragma unroll
                for (int nb = 0; nb < 8; ++nb)
                    mma_fp16(c[mb][nb][0], c[mb][nb][1], c[mb][nb][2], c[mb][nb][3],
                             a[mb][0], a[mb][1], a[mb][2], a[mb][3],
                             bf[nb][0], bf[nb][1]);
        }
    }
    __syncthreads();

    // ---- epilogue: stage fp16 M tile in smem, then coalesced store ----
    __half* sM = smem;   // [128 co][MSTR]
#pragma unroll
    for (int mb = 0; mb < 2; ++mb) {
        int r0 = wm*32 + mb*16 + g;
        int col = wn*64 + 2*t4;
#pragma unroll
        for (int nb = 0; nb < 8; ++nb) {
            __half2 h01 = __floats2half2_rn(c[mb][nb][0], c[mb][nb][1]);
            __half2 h23 = __floats2half2_rn(c[mb][nb][2], c[mb][nb][3]);
            *(__half2*)(sM + r0*MSTR + col + nb*8) = h01;
            *(__half2*)(sM + (r0+8)*MSTR + col + nb*8) = h23;
        }
    }
    __syncthreads();
#pragma unroll
    for (int it = 0; it < 8; ++it) {
        int lin = it*256 + t;
        int row = lin >> 4, q = lin & 15;
        uint4 v = *(const uint4*)(sM + row*MSTR + q*8);
        *(uint4*)(g_M + ((size_t)(tap*COUT + coT*128 + row))*NT
                        + Tbase + q*8) = v;
    }
}

// ================= kernel B: inverse transform + demod scale ==========
// grid (16 tG, 32 coG, 16 b), 256 thr; warp=co, lane handles 2 tiles (half2)
__global__ __launch_bounds__(256)
void k_inv(float* __restrict__ out) {
    const int lane = threadIdx.x & 31;
    const int wid  = threadIdx.x >> 5;
    const int tG   = blockIdx.x;
    const int co   = blockIdx.y*8 + wid;
    const int b    = blockIdx.z;
    const int T    = b*1024 + tG*64 + lane*2;

    float2 m[16];
#pragma unroll
    for (int tap = 0; tap < 16; ++tap) {
        __half2 h = *(const __half2*)(g_M + ((size_t)(tap*COUT + co))*NT + T);
        m[tap] = __half22float2(h);
    }

    float sc = g_scale[b*COUT + co];
    int rel = (tG*64 + lane*2) & 1023;
    int tyy = rel >> 5, txx = rel & 31;       // txx even
    float* ob = out + (((size_t)(b*COUT + co)) << 12) + (2*tyy)*64 + 2*txx;

    float4 row0, row1;
    {   // element 0
        float t0[4], t1[4];
#pragma unroll
        for (int cc = 0; cc < 4; ++cc) {
            t0[cc] = m[cc].x + m[4+cc].x + m[8+cc].x;
            t1[cc] = m[4+cc].x - m[8+cc].x - m[12+cc].x;
        }
        row0.x = sc*(t0[0] + t0[1] + t0[2]);
        row0.y = sc*(t0[1] - t0[2] - t0[3]);
        row1.x = sc*(t1[0] + t1[1] + t1[2]);
        row1.y = sc*(t1[1] - t1[2] - t1[3]);
    }
    {   // element 1
        float t0[4], t1[4];
#pragma unroll
        for (int cc = 0; cc < 4; ++cc) {
            t0[cc] = m[cc].y + m[4+cc].y + m[8+cc].y;
            t1[cc] = m[4+cc].y - m[8+cc].y - m[12+cc].y;
        }
        row0.z = sc*(t0[0] + t0[1] + t0[2]);
        row0.w = sc*(t0[1] - t0[2] - t0[3]);
        row1.z = sc*(t1[0] + t1[1] + t1[2]);
        row1.w = sc*(t1[1] - t1[2] - t1[3]);
    }
    *(float4*)(ob)      = row0;
    *(float4*)(ob + 64) = row1;
}

// ================= launcher =================
extern "C" void kernel_launch(void* const* d_in, const int* in_sizes, int n_in,
                              void* d_out, int out_size) {
    const float* x = (const float*)d_in[0];   // [B, CIN, 64, 64]
    const float* s = (const float*)d_in[1];   // [B, CIN]
    const float* w = (const float*)d_in[2];   // [COUT, CIN, 3, 3]
    float* out = (float*)d_out;               // [B, COUT, 64, 64]

    cudaFuncSetAttribute(k_gemm, cudaFuncAttributeMaxDynamicSharedMemorySize,
                         GSMEM_BYTES);
    cudaFuncSetAttribute(k_wino_x, cudaFuncAttributeMaxDynamicSharedMemorySize,
                         XS_BYTES);

    k_snorm<<<1, 256>>>(s);
    k_wprep<<<COUT, 256>>>(w);
    dim3 gs(COUT, B_);
    k_scale<<<gs, 256>>>(s);
    dim3 gx(8, 8, B_);
    k_wino_x<<<gx, 256, XS_BYTES>>>(x, s);
    dim3 gg(2, 128, 16);
    k_gemm<<<gg, 256, GSMEM_BYTES>>>();
    dim3 gi(16, 32, B_);
    k_inv<<<gi, 256>>>(out);
}

// round 11
// speedup vs baseline: 1.0952x; 1.0952x over previous
#include <cuda_runtime.h>
#include <cuda_fp16.h>
#include <cstdint>

// Problem constants
#define B_    16
#define CIN   256
#define COUT  256
#define EPS_F 1e-8f
#define NT    16384            // Winograd tiles total (16 b * 32 * 32)

// ================= scratch =================
__device__ float g_snorm;
__device__ float g_wsq[COUT*CIN];
__device__ float g_invwn[COUT];
__device__ float g_scale[B_*COUT];
// V: [tap 16][T 16384][ci 256] fp16 (134MB)
__device__ __align__(16) __half g_V[(size_t)16*NT*CIN];
// U: [tap 16][co 256][ci 256] fp16 (2MB)
__device__ __align__(16) __half g_U[16*COUT*CIN];
// M: [tap 16][co 256][T 16384] fp16 (134MB)
__device__ __align__(16) __half g_M[(size_t)16*COUT*NT];

// ================= helpers =================
__device__ __forceinline__ void mma_fp16(float& d0, float& d1, float& d2, float& d3,
                                         uint32_t a0, uint32_t a1, uint32_t a2, uint32_t a3,
                                         uint32_t b0, uint32_t b1) {
    asm volatile("mma.sync.aligned.m16n8k16.row.col.f32.f16.f16.f32 "
                 "{%0,%1,%2,%3}, {%4,%5,%6,%7}, {%8,%9}, {%0,%1,%2,%3};"
                 : "+f"(d0), "+f"(d1), "+f"(d2), "+f"(d3)
                 : "r"(a0), "r"(a1), "r"(a2), "r"(a3), "r"(b0), "r"(b1));
}
__device__ __forceinline__ void cp_async16(uint32_t saddr, const void* gaddr) {
    asm volatile("cp.async.cg.shared.global [%0], [%1], 16;"
                 :: "r"(saddr), "l"(gaddr) : "memory");
}
__device__ __forceinline__ void cp_commit() {
    asm volatile("cp.async.commit_group;" ::: "memory");
}
__device__ __forceinline__ void cp_wait2() {
    asm volatile("cp.async.wait_group 2;" ::: "memory");
}
__device__ __forceinline__ uint32_t smem_u32(const void* p) {
    uint32_t a;
    asm("{ .reg .u64 t; cvta.to.shared.u64 t, %1; cvt.u32.u64 %0, t; }"
        : "=r"(a) : "l"(p));
    return a;
}

// ================= norm/scale kernels =================
__global__ void k_snorm(const float* __restrict__ s) {
    __shared__ float red[256];
    float acc = 0.f;
    for (int i = threadIdx.x; i < B_*CIN; i += 256) { float v = s[i]; acc += v*v; }
    red[threadIdx.x] = acc; __syncthreads();
    for (int off = 128; off > 0; off >>= 1) {
        if (threadIdx.x < off) red[threadIdx.x] += red[threadIdx.x + off];
        __syncthreads();
    }
    if (threadIdx.x == 0) g_snorm = rsqrtf(red[0] / (float)(B_*CIN));
}

// merged: weight stats + Winograd weight transform (single w read)
__global__ void k_wprep(const float* __restrict__ w) {
    __shared__ float red[256];
    int co = blockIdx.x, ci = threadIdx.x;
    const float* gp = w + ((size_t)co*CIN + ci)*9;
    float g0[3], g1[3], g2[3];
#pragma unroll
    for (int c = 0; c < 3; ++c) { g0[c]=gp[c]; g1[c]=gp[3+c]; g2[c]=gp[6+c]; }
    float s9 = 0.f;
#pragma unroll
    for (int c = 0; c < 3; ++c) s9 += g0[c]*g0[c] + g1[c]*g1[c] + g2[c]*g2[c];
    g_wsq[co*CIN + ci] = s9;
    red[ci] = s9; __syncthreads();
    for (int off = 128; off > 0; off >>= 1) {
        if (ci < off) red[ci] += red[ci + off];
        __syncthreads();
    }
    if (ci == 0) g_invwn[co] = rsqrtf(red[0] / (float)(CIN*9));

    float tm[4][3];
#pragma unroll
    for (int c = 0; c < 3; ++c) {
        tm[0][c] = g0[c];
        tm[1][c] = 0.5f*(g0[c] + g1[c] + g2[c]);
        tm[2][c] = 0.5f*(g0[c] - g1[c] + g2[c]);
        tm[3][c] = g2[c];
    }
#pragma unroll
    for (int r = 0; r < 4; ++r) {
        float u0 = tm[r][0];
        float u1 = 0.5f*(tm[r][0] + tm[r][1] + tm[r][2]);
        float u2 = 0.5f*(tm[r][0] - tm[r][1] + tm[r][2]);
        float u3 = tm[r][2];
        g_U[(((size_t)((r*4+0)*COUT + co))<<8) + ci] = __float2half_rn(u0);
        g_U[(((size_t)((r*4+1)*COUT + co))<<8) + ci] = __float2half_rn(u1);
        g_U[(((size_t)((r*4+2)*COUT + co))<<8) + ci] = __float2half_rn(u2);
        g_U[(((size_t)((r*4+3)*COUT + co))<<8) + ci] = __float2half_rn(u3);
    }
}

__global__ void k_scale(const float* __restrict__ s) {
    __shared__ float red[256];
    int co = blockIdx.x, b = blockIdx.y, ci = threadIdx.x;
    float sn = s[b*CIN + ci] * g_snorm;
    red[ci] = sn*sn * g_wsq[co*CIN + ci]; __syncthreads();
    for (int off = 128; off > 0; off >>= 1) {
        if (ci < off) red[ci] += red[ci + off];
        __syncthreads();
    }
    if (ci == 0) {
        float iw = g_invwn[co];
        g_scale[b*COUT + co] = iw * rsqrtf(iw*iw*red[0] + EPS_F);
    }
}

// ================= input transform: V = B^T (x*s*snorm) B =================
// R9-proven shape: grid (32 ty, 8 ciT, 16 b), 256 threads, static 34.3KB smem
__global__ void k_wino_x(const float* __restrict__ x, const float* __restrict__ s) {
    __shared__ float sm[4][32][67];
    const int tid = threadIdx.x;
    const int ty = blockIdx.x, ciT = blockIdx.y, b = blockIdx.z;
    const float snorm = g_snorm;
    const int r0 = 2*ty - 1;
#pragma unroll
    for (int k = 0; k < 8; ++k) {
        int lin = k*256 + tid;            // (ci 32)(r 4)(c4 16)
        int c4 = lin & 15, r = (lin >> 4) & 3, ci = lin >> 6;
        int gci = ciT*32 + ci;
        int gr = r0 + r;
        float4 v = make_float4(0.f, 0.f, 0.f, 0.f);
        if ((unsigned)gr < 64u)
            v = *(const float4*)(x + (((size_t)(b*CIN + gci)) << 12) + gr*64 + c4*4);
        float m = s[b*CIN + gci] * snorm;
        float* d = &sm[r][ci][1 + 4*c4];
        d[0] = v.x*m; d[1] = v.y*m; d[2] = v.z*m; d[3] = v.w*m;
        if (c4 == 0)  sm[r][ci][0]  = 0.f;
        if (c4 == 15) sm[r][ci][65] = 0.f;
    }
    __syncthreads();
    const int ci = tid & 31, txq = tid >> 5;
#pragma unroll
    for (int k = 0; k < 4; ++k) {
        int tx = txq + 8*k;
        float d[4][4];
#pragma unroll
        for (int r = 0; r < 4; ++r)
#pragma unroll
            for (int c = 0; c < 4; ++c) d[r][c] = sm[r][ci][2*tx + c];
        float m0[4], m1[4], m2[4], m3[4];
#pragma unroll
        for (int j = 0; j < 4; ++j) {
            m0[j] = d[0][j] - d[2][j];
            m1[j] = d[1][j] + d[2][j];
            m2[j] = d[2][j] - d[1][j];
            m3[j] = d[1][j] - d[3][j];
        }
        float V[4][4];
#pragma unroll
        for (int r = 0; r < 4; ++r) {
            const float* mr = (r==0)?m0:(r==1)?m1:(r==2)?m2:m3;
            V[r][0] = mr[0] - mr[2];
            V[r][1] = mr[1] + mr[2];
            V[r][2] = mr[2] - mr[1];
            V[r][3] = mr[1] - mr[3];
        }
        int T = b*1024 + ty*32 + tx;
#pragma unroll
        for (int r = 0; r < 4; ++r)
#pragma unroll
            for (int c = 0; c < 4; ++c)
                g_V[(((size_t)((r*4+c)*NT + T)) << 8) + ciT*32 + ci] =
                    __float2half_rn(V[r][c]);
    }
}

// ================= kernel A: batched GEMM  M[tap] = U[tap] x V[tap] ====
// CTA 128co x 128T, warp m32 x n64 (8 warps: wm=wid&3, wn=wid>>2).
// K=256 in 8 phases of 32. 4-stage cp.async, one barrier/phase, 2 CTA/SM.
#define KSTR 40
#define AT_HALFS (128*KSTR)                      // 5120
#define STG_HALFS (2*AT_HALFS)                   // 10240
#define GSMEM_BYTES (4*STG_HALFS*2)              // 81920
#define MSTR 136

__global__ __launch_bounds__(256, 2)
void k_gemm() {
    extern __shared__ __half smem[];
    const uint32_t smem_base = smem_u32(smem);

    const int t    = threadIdx.x;
    const int lane = t & 31;
    const int wm   = (t >> 5) & 3;        // m32 block
    const int wn   = t >> 7;              // n64 block
    const int g    = lane >> 2;
    const int t4   = lane & 3;

    const int coT   = blockIdx.x;         // 0..1 (fastest: shares V slab in L2)
    const int Tbase = blockIdx.y * 128;
    const int tap   = blockIdx.z;

    float c[2][8][4];
#pragma unroll
    for (int mb = 0; mb < 2; ++mb)
#pragma unroll
        for (int nb = 0; nb < 8; ++nb)
#pragma unroll
            for (int q = 0; q < 4; ++q) c[mb][nb][q] = 0.f;

    auto load_phase = [&](int p, int j) {
        uint32_t sbase = smem_base + (j*STG_HALFS)*2;
#pragma unroll
        for (int k2 = 0; k2 < 2; ++k2) {
            int lin = k2*256 + t;
            int row = lin >> 2, q = lin & 3;
            const __half* src = g_U + (((size_t)(tap*COUT + coT*128 + row)) << 8)
                              + p*32 + q*8;
            cp_async16(sbase + (row*KSTR + q*8)*2, src);
        }
#pragma unroll
        for (int k2 = 0; k2 < 2; ++k2) {
            int lin = k2*256 + t;
            int row = lin >> 2, q = lin & 3;
            const __half* src = g_V + (((size_t)(tap*NT + Tbase + row)) << 8)
                              + p*32 + q*8;
            cp_async16(sbase + (AT_HALFS + row*KSTR + q*8)*2, src);
        }
    };

#pragma unroll
    for (int p = 0; p < 3; ++p) { load_phase(p, p); cp_commit(); }

    for (int p = 0; p < 8; ++p) {
        const int j = p & 3;
        cp_wait2();
        __syncthreads();
        if (p + 3 < 8) load_phase(p + 3, (p + 3) & 3);
        cp_commit();

        const __half* A  = smem + j*STG_HALFS;
        const __half* Bm = A + AT_HALFS;
#pragma unroll
        for (int ks = 0; ks < 2; ++ks) {
            uint32_t a[2][4];
#pragma unroll
            for (int mb = 0; mb < 2; ++mb) {
                const __half* ap = A + (wm*32 + mb*16 + g)*KSTR + ks*16 + 2*t4;
                a[mb][0] = *(const uint32_t*)(ap);
                a[mb][1] = *(const uint32_t*)(ap + 8*KSTR);
                a[mb][2] = *(const uint32_t*)(ap + 8);
                a[mb][3] = *(const uint32_t*)(ap + 8*KSTR + 8);
            }
            uint32_t bf[8][2];
#pragma unroll
            for (int nb = 0; nb < 8; ++nb) {
                const __half* bp = Bm + (wn*64 + nb*8 + g)*KSTR + ks*16 + 2*t4;
                bf[nb][0] = *(const uint32_t*)(bp);
                bf[nb][1] = *(const uint32_t*)(bp + 8);
            }
#pragma unroll
            for (int mb = 0; mb < 2; ++mb)
#pragma unroll
                for (int nb = 0; nb < 8; ++nb)
                    mma_fp16(c[mb][nb][0], c[mb][nb][1], c[mb][nb][2], c[mb][nb][3],
                             a[mb][0], a[mb][1], a[mb][2], a[mb][3],
                             bf[nb][0], bf[nb][1]);
        }
    }
    __syncthreads();

    // ---- epilogue: stage fp16 M tile in smem, then coalesced store ----
    __half* sM = smem;   // [128 co][MSTR]
#pragma unroll
    for (int mb = 0; mb < 2; ++mb) {
        int r0 = wm*32 + mb*16 + g;
        int col = wn*64 + 2*t4;
#pragma unroll
        for (int nb = 0; nb < 8; ++nb) {
            __half2 h01 = __floats2half2_rn(c[mb][nb][0], c[mb][nb][1]);
            __half2 h23 = __floats2half2_rn(c[mb][nb][2], c[mb][nb][3]);
            *(__half2*)(sM + r0*MSTR + col + nb*8) = h01;
            *(__half2*)(sM + (r0+8)*MSTR + col + nb*8) = h23;
        }
    }
    __syncthreads();
#pragma unroll
    for (int it = 0; it < 8; ++it) {
        int lin = it*256 + t;
        int row = lin >> 4, q = lin & 15;
        uint4 v = *(const uint4*)(sM + row*MSTR + q*8);
        *(uint4*)(g_M + ((size_t)(tap*COUT + coT*128 + row))*NT
                        + Tbase + q*8) = v;
    }
}

// ================= kernel B: inverse transform + demod scale ==========
// grid (16 tG, 32 coG, 16 b), 256 thr; warp=co, lane handles 2 tiles (half2)
__global__ __launch_bounds__(256)
void k_inv(float* __restrict__ out) {
    const int lane = threadIdx.x & 31;
    const int wid  = threadIdx.x >> 5;
    const int tG   = blockIdx.x;
    const int co   = blockIdx.y*8 + wid;
    const int b    = blockIdx.z;
    const int T    = b*1024 + tG*64 + lane*2;

    float2 m[16];
#pragma unroll
    for (int tap = 0; tap < 16; ++tap) {
        __half2 h = *(const __half2*)(g_M + ((size_t)(tap*COUT + co))*NT + T);
        m[tap] = __half22float2(h);
    }

    float sc = g_scale[b*COUT + co];
    int rel = (tG*64 + lane*2) & 1023;
    int tyy = rel >> 5, txx = rel & 31;       // txx even
    float* ob = out + (((size_t)(b*COUT + co)) << 12) + (2*tyy)*64 + 2*txx;

    float4 row0, row1;
    {   // element 0
        float t0[4], t1[4];
#pragma unroll
        for (int cc = 0; cc < 4; ++cc) {
            t0[cc] = m[cc].x + m[4+cc].x + m[8+cc].x;
            t1[cc] = m[4+cc].x - m[8+cc].x - m[12+cc].x;
        }
        row0.x = sc*(t0[0] + t0[1] + t0[2]);
        row0.y = sc*(t0[1] - t0[2] - t0[3]);
        row1.x = sc*(t1[0] + t1[1] + t1[2]);
        row1.y = sc*(t1[1] - t1[2] - t1[3]);
    }
    {   // element 1
        float t0[4], t1[4];
#pragma unroll
        for (int cc = 0; cc < 4; ++cc) {
            t0[cc] = m[cc].y + m[4+cc].y + m[8+cc].y;
            t1[cc] = m[4+cc].y - m[8+cc].y - m[12+cc].y;
        }
        row0.z = sc*(t0[0] + t0[1] + t0[2]);
        row0.w = sc*(t0[1] - t0[2] - t0[3]);
        row1.z = sc*(t1[0] + t1[1] + t1[2]);
        row1.w = sc*(t1[1] - t1[2] - t1[3]);
    }
    *(float4*)(ob)      = row0;
    *(float4*)(ob + 64) = row1;
}

// ================= launcher =================
extern "C" void kernel_launch(void* const* d_in, const int* in_sizes, int n_in,
                              void* d_out, int out_size) {
    const float* x = (const float*)d_in[0];   // [B, CIN, 64, 64]
    const float* s = (const float*)d_in[1];   // [B, CIN]
    const float* w = (const float*)d_in[2];   // [COUT, CIN, 3, 3]
    float* out = (float*)d_out;               // [B, COUT, 64, 64]

    cudaFuncSetAttribute(k_gemm, cudaFuncAttributeMaxDynamicSharedMemorySize,
                         GSMEM_BYTES);

    k_snorm<<<1, 256>>>(s);
    k_wprep<<<COUT, 256>>>(w);
    dim3 gs(COUT, B_);
    k_scale<<<gs, 256>>>(s);
    dim3 gx(32, 8, B_);
    k_wino_x<<<gx, 256>>>(x, s);
    dim3 gg(2, 128, 16);
    k_gemm<<<gg, 256, GSMEM_BYTES>>>();
    dim3 gi(16, 32, B_);
    k_inv<<<gi, 256>>>(out);
}

// round 12
// speedup vs baseline: 1.2170x; 1.1112x over previous
#include <cuda_runtime.h>
#include <cuda_fp16.h>
#include <cstdint>

// Problem constants
#define B_    16
#define CIN   256
#define COUT  256
#define EPS_F 1e-8f
#define NT    16384            // Winograd tiles total (16 b * 32 * 32)

// ================= scratch =================
__device__ float g_snorm;
__device__ float g_wsq[COUT*CIN];
__device__ float g_invwn[COUT];
__device__ float g_scale[B_*COUT];
// V: [tap 16][T 16384][ci 256] fp16 (134MB)
__device__ __align__(16) __half g_V[(size_t)16*NT*CIN];
// U: [tap 16][co 256][ci 256] fp16 (2MB)
__device__ __align__(16) __half g_U[16*COUT*CIN];
// M: [tap 16][co 256][T 16384] fp16 (134MB)
__device__ __align__(16) __half g_M[(size_t)16*COUT*NT];

// ================= helpers =================
__device__ __forceinline__ void mma_fp16(float& d0, float& d1, float& d2, float& d3,
                                         uint32_t a0, uint32_t a1, uint32_t a2, uint32_t a3,
                                         uint32_t b0, uint32_t b1) {
    asm volatile("mma.sync.aligned.m16n8k16.row.col.f32.f16.f16.f32 "
                 "{%0,%1,%2,%3}, {%4,%5,%6,%7}, {%8,%9}, {%0,%1,%2,%3};"
                 : "+f"(d0), "+f"(d1), "+f"(d2), "+f"(d3)
                 : "r"(a0), "r"(a1), "r"(a2), "r"(a3), "r"(b0), "r"(b1));
}
__device__ __forceinline__ void cp_async16(uint32_t saddr, const void* gaddr) {
    asm volatile("cp.async.cg.shared.global [%0], [%1], 16;"
                 :: "r"(saddr), "l"(gaddr) : "memory");
}
__device__ __forceinline__ void cp_commit() {
    asm volatile("cp.async.commit_group;" ::: "memory");
}
__device__ __forceinline__ void cp_wait1() {
    asm volatile("cp.async.wait_group 1;" ::: "memory");
}
__device__ __forceinline__ uint32_t smem_u32(const void* p) {
    uint32_t a;
    asm("{ .reg .u64 t; cvta.to.shared.u64 t, %1; cvt.u32.u64 %0, t; }"
        : "=r"(a) : "l"(p));
    return a;
}

// ================= norm/scale kernels =================
__global__ void k_snorm(const float* __restrict__ s) {
    __shared__ float red[256];
    float acc = 0.f;
    for (int i = threadIdx.x; i < B_*CIN; i += 256) { float v = s[i]; acc += v*v; }
    red[threadIdx.x] = acc; __syncthreads();
    for (int off = 128; off > 0; off >>= 1) {
        if (threadIdx.x < off) red[threadIdx.x] += red[threadIdx.x + off];
        __syncthreads();
    }
    if (threadIdx.x == 0) g_snorm = rsqrtf(red[0] / (float)(B_*CIN));
}

// merged: weight stats + Winograd weight transform (single w read)
__global__ void k_wprep(const float* __restrict__ w) {
    __shared__ float red[256];
    int co = blockIdx.x, ci = threadIdx.x;
    const float* gp = w + ((size_t)co*CIN + ci)*9;
    float g0[3], g1[3], g2[3];
#pragma unroll
    for (int c = 0; c < 3; ++c) { g0[c]=gp[c]; g1[c]=gp[3+c]; g2[c]=gp[6+c]; }
    float s9 = 0.f;
#pragma unroll
    for (int c = 0; c < 3; ++c) s9 += g0[c]*g0[c] + g1[c]*g1[c] + g2[c]*g2[c];
    g_wsq[co*CIN + ci] = s9;
    red[ci] = s9; __syncthreads();
    for (int off = 128; off > 0; off >>= 1) {
        if (ci < off) red[ci] += red[ci + off];
        __syncthreads();
    }
    if (ci == 0) g_invwn[co] = rsqrtf(red[0] / (float)(CIN*9));

    float tm[4][3];
#pragma unroll
    for (int c = 0; c < 3; ++c) {
        tm[0][c] = g0[c];
        tm[1][c] = 0.5f*(g0[c] + g1[c] + g2[c]);
        tm[2][c] = 0.5f*(g0[c] - g1[c] + g2[c]);
        tm[3][c] = g2[c];
    }
#pragma unroll
    for (int r = 0; r < 4; ++r) {
        float u0 = tm[r][0];
        float u1 = 0.5f*(tm[r][0] + tm[r][1] + tm[r][2]);
        float u2 = 0.5f*(tm[r][0] - tm[r][1] + tm[r][2]);
        float u3 = tm[r][2];
        g_U[(((size_t)((r*4+0)*COUT + co))<<8) + ci] = __float2half_rn(u0);
        g_U[(((size_t)((r*4+1)*COUT + co))<<8) + ci] = __float2half_rn(u1);
        g_U[(((size_t)((r*4+2)*COUT + co))<<8) + ci] = __float2half_rn(u2);
        g_U[(((size_t)((r*4+3)*COUT + co))<<8) + ci] = __float2half_rn(u3);
    }
}

__global__ void k_scale(const float* __restrict__ s) {
    __shared__ float red[256];
    int co = blockIdx.x, b = blockIdx.y, ci = threadIdx.x;
    float sn = s[b*CIN + ci] * g_snorm;
    red[ci] = sn*sn * g_wsq[co*CIN + ci]; __syncthreads();
    for (int off = 128; off > 0; off >>= 1) {
        if (ci < off) red[ci] += red[ci + off];
        __syncthreads();
    }
    if (ci == 0) {
        float iw = g_invwn[co];
        g_scale[b*COUT + co] = iw * rsqrtf(iw*iw*red[0] + EPS_F);
    }
}

// ================= input transform: V = B^T (x*s*snorm) B =================
// R9/R11-proven shape: grid (32 ty, 8 ciT, 16 b), 256 threads, 34.3KB smem
__global__ void k_wino_x(const float* __restrict__ x, const float* __restrict__ s) {
    __shared__ float sm[4][32][67];
    const int tid = threadIdx.x;
    const int ty = blockIdx.x, ciT = blockIdx.y, b = blockIdx.z;
    const float snorm = g_snorm;
    const int r0 = 2*ty - 1;
#pragma unroll
    for (int k = 0; k < 8; ++k) {
        int lin = k*256 + tid;            // (ci 32)(r 4)(c4 16)
        int c4 = lin & 15, r = (lin >> 4) & 3, ci = lin >> 6;
        int gci = ciT*32 + ci;
        int gr = r0 + r;
        float4 v = make_float4(0.f, 0.f, 0.f, 0.f);
        if ((unsigned)gr < 64u)
            v = *(const float4*)(x + (((size_t)(b*CIN + gci)) << 12) + gr*64 + c4*4);
        float m = s[b*CIN + gci] * snorm;
        float* d = &sm[r][ci][1 + 4*c4];
        d[0] = v.x*m; d[1] = v.y*m; d[2] = v.z*m; d[3] = v.w*m;
        if (c4 == 0)  sm[r][ci][0]  = 0.f;
        if (c4 == 15) sm[r][ci][65] = 0.f;
    }
    __syncthreads();
    const int ci = tid & 31, txq = tid >> 5;
#pragma unroll
    for (int k = 0; k < 4; ++k) {
        int tx = txq + 8*k;
        float d[4][4];
#pragma unroll
        for (int r = 0; r < 4; ++r)
#pragma unroll
            for (int c = 0; c < 4; ++c) d[r][c] = sm[r][ci][2*tx + c];
        float m0[4], m1[4], m2[4], m3[4];
#pragma unroll
        for (int j = 0; j < 4; ++j) {
            m0[j] = d[0][j] - d[2][j];
            m1[j] = d[1][j] + d[2][j];
            m2[j] = d[2][j] - d[1][j];
            m3[j] = d[1][j] - d[3][j];
        }
        float V[4][4];
#pragma unroll
        for (int r = 0; r < 4; ++r) {
            const float* mr = (r==0)?m0:(r==1)?m1:(r==2)?m2:m3;
            V[r][0] = mr[0] - mr[2];
            V[r][1] = mr[1] + mr[2];
            V[r][2] = mr[2] - mr[1];
            V[r][3] = mr[1] - mr[3];
        }
        int T = b*1024 + ty*32 + tx;
#pragma unroll
        for (int r = 0; r < 4; ++r)
#pragma unroll
            for (int c = 0; c < 4; ++c)
                g_V[(((size_t)((r*4+c)*NT + T)) << 8) + ciT*32 + ci] =
                    __float2half_rn(V[r][c]);
    }
}

// ================= kernel A: batched GEMM  M[tap] = U[tap] x V[tap] ====
// CTA 128co x 128T, warp m32 x n64 (8 warps: wm=wid&3, wn=wid>>2).
// K=256 in 4 phases of 64. 3-stage cp.async, wait_group 1, 2 CTA/SM.
#define KSTR 72
#define AT_HALFS (128*KSTR)                      // 9216
#define STG_HALFS (2*AT_HALFS)                   // 18432
#define GSMEM_BYTES (3*STG_HALFS*2)              // 110592
#define MSTR 136

__global__ __launch_bounds__(256, 2)
void k_gemm() {
    extern __shared__ __half smem[];
    const uint32_t smem_base = smem_u32(smem);

    const int t    = threadIdx.x;
    const int lane = t & 31;
    const int wm   = (t >> 5) & 3;        // m32 block
    const int wn   = t >> 7;              // n64 block
    const int g    = lane >> 2;
    const int t4   = lane & 3;

    const int coT   = blockIdx.x;         // 0..1 (fastest: shares V slab in L2)
    const int Tbase = blockIdx.y * 128;
    const int tap   = blockIdx.z;

    float c[2][8][4];
#pragma unroll
    for (int mb = 0; mb < 2; ++mb)
#pragma unroll
        for (int nb = 0; nb < 8; ++nb)
#pragma unroll
            for (int q = 0; q < 4; ++q) c[mb][nb][q] = 0.f;

    // phase = 64 k-columns. A: 128 rows x 8 uint4; B: 128 rows x 8 uint4.
    auto load_phase = [&](int p, int j) {
        uint32_t sbase = smem_base + (j*STG_HALFS)*2;
#pragma unroll
        for (int k4 = 0; k4 < 4; ++k4) {
            int lin = k4*256 + t;
            int row = lin >> 3, q = lin & 7;
            const __half* src = g_U + (((size_t)(tap*COUT + coT*128 + row)) << 8)
                              + p*64 + q*8;
            cp_async16(sbase + (row*KSTR + q*8)*2, src);
        }
#pragma unroll
        for (int k4 = 0; k4 < 4; ++k4) {
            int lin = k4*256 + t;
            int row = lin >> 3, q = lin & 7;
            const __half* src = g_V + (((size_t)(tap*NT + Tbase + row)) << 8)
                              + p*64 + q*8;
            cp_async16(sbase + (AT_HALFS + row*KSTR + q*8)*2, src);
        }
    };

    // prologue: phases 0,1 into slots 0,1
    load_phase(0, 0); cp_commit();
    load_phase(1, 1); cp_commit();

    for (int p = 0; p < 4; ++p) {
        const int j = p % 3;
        cp_wait1();             // phase p resident; p+1 in flight
        __syncthreads();        // slot (p-1)%3 reusable after this
        if (p + 2 < 4) load_phase(p + 2, (p + 2) % 3);
        cp_commit();            // invariant group count

        const __half* A  = smem + j*STG_HALFS;
        const __half* Bm = A + AT_HALFS;
#pragma unroll
        for (int ks = 0; ks < 4; ++ks) {
            uint32_t a[2][4];
#pragma unroll
            for (int mb = 0; mb < 2; ++mb) {
                const __half* ap = A + (wm*32 + mb*16 + g)*KSTR + ks*16 + 2*t4;
                a[mb][0] = *(const uint32_t*)(ap);
                a[mb][1] = *(const uint32_t*)(ap + 8*KSTR);
                a[mb][2] = *(const uint32_t*)(ap + 8);
                a[mb][3] = *(const uint32_t*)(ap + 8*KSTR + 8);
            }
            uint32_t bf[8][2];
#pragma unroll
            for (int nb = 0; nb < 8; ++nb) {
                const __half* bp = Bm + (wn*64 + nb*8 + g)*KSTR + ks*16 + 2*t4;
                bf[nb][0] = *(const uint32_t*)(bp);
                bf[nb][1] = *(const uint32_t*)(bp + 8);
            }
#pragma unroll
            for (int mb = 0; mb < 2; ++mb)
#pragma unroll
                for (int nb = 0; nb < 8; ++nb)
                    mma_fp16(c[mb][nb][0], c[mb][nb][1], c[mb][nb][2], c[mb][nb][3],
                             a[mb][0], a[mb][1], a[mb][2], a[mb][3],
                             bf[nb][0], bf[nb][1]);
        }
    }
    __syncthreads();

    // ---- epilogue: stage fp16 M tile in smem, then coalesced store ----
    __half* sM = smem;   // [128 co][MSTR]
#pragma unroll
    for (int mb = 0; mb < 2; ++mb) {
        int r0 = wm*32 + mb*16 + g;
        int col = wn*64 + 2*t4;
#pragma unroll
        for (int nb = 0; nb < 8; ++nb) {
            __half2 h01 = __floats2half2_rn(c[mb][nb][0], c[mb][nb][1]);
            __half2 h23 = __floats2half2_rn(c[mb][nb][2], c[mb][nb][3]);
            *(__half2*)(sM + r0*MSTR + col + nb*8) = h01;
            *(__half2*)(sM + (r0+8)*MSTR + col + nb*8) = h23;
        }
    }
    __syncthreads();
#pragma unroll
    for (int it = 0; it < 8; ++it) {
        int lin = it*256 + t;
        int row = lin >> 4, q = lin & 15;
        uint4 v = *(const uint4*)(sM + row*MSTR + q*8);
        *(uint4*)(g_M + ((size_t)(tap*COUT + coT*128 + row))*NT
                        + Tbase + q*8) = v;
    }
}

// ================= kernel B: inverse transform + demod scale ==========
// grid (16 tG, 32 coG, 16 b), 256 thr; warp=co, lane handles 2 tiles (half2)
__global__ __launch_bounds__(256)
void k_inv(float* __restrict__ out) {
    const int lane = threadIdx.x & 31;
    const int wid  = threadIdx.x >> 5;
    const int tG   = blockIdx.x;
    const int co   = blockIdx.y*8 + wid;
    const int b    = blockIdx.z;
    const int T    = b*1024 + tG*64 + lane*2;

    float2 m[16];
#pragma unroll
    for (int tap = 0; tap < 16; ++tap) {
        __half2 h = *(const __half2*)(g_M + ((size_t)(tap*COUT + co))*NT + T);
        m[tap] = __half22float2(h);
    }

    float sc = g_scale[b*COUT + co];
    int rel = (tG*64 + lane*2) & 1023;
    int tyy = rel >> 5, txx = rel & 31;       // txx even
    float* ob = out + (((size_t)(b*COUT + co)) << 12) + (2*tyy)*64 + 2*txx;

    float4 row0, row1;
    {   // element 0
        float t0[4], t1[4];
#pragma unroll
        for (int cc = 0; cc < 4; ++cc) {
            t0[cc] = m[cc].x + m[4+cc].x + m[8+cc].x;
            t1[cc] = m[4+cc].x - m[8+cc].x - m[12+cc].x;
        }
        row0.x = sc*(t0[0] + t0[1] + t0[2]);
        row0.y = sc*(t0[1] - t0[2] - t0[3]);
        row1.x = sc*(t1[0] + t1[1] + t1[2]);
        row1.y = sc*(t1[1] - t1[2] - t1[3]);
    }
    {   // element 1
        float t0[4], t1[4];
#pragma unroll
        for (int cc = 0; cc < 4; ++cc) {
            t0[cc] = m[cc].y + m[4+cc].y + m[8+cc].y;
            t1[cc] = m[4+cc].y - m[8+cc].y - m[12+cc].y;
        }
        row0.z = sc*(t0[0] + t0[1] + t0[2]);
        row0.w = sc*(t0[1] - t0[2] - t0[3]);
        row1.z = sc*(t1[0] + t1[1] + t1[2]);
        row1.w = sc*(t1[1] - t1[2] - t1[3]);
    }
    *(float4*)(ob)      = row0;
    *(float4*)(ob + 64) = row1;
}

// ================= launcher =================
extern "C" void kernel_launch(void* const* d_in, const int* in_sizes, int n_in,
                              void* d_out, int out_size) {
    const float* x = (const float*)d_in[0];   // [B, CIN, 64, 64]
    const float* s = (const float*)d_in[1];   // [B, CIN]
    const float* w = (const float*)d_in[2];   // [COUT, CIN, 3, 3]
    float* out = (float*)d_out;               // [B, COUT, 64, 64]

    cudaFuncSetAttribute(k_gemm, cudaFuncAttributeMaxDynamicSharedMemorySize,
                         GSMEM_BYTES);

    k_snorm<<<1, 256>>>(s);
    k_wprep<<<COUT, 256>>>(w);
    dim3 gs(COUT, B_);
    k_scale<<<gs, 256>>>(s);
    dim3 gx(32, 8, B_);
    k_wino_x<<<gx, 256>>>(x, s);
    dim3 gg(2, 128, 16);
    k_gemm<<<gg, 256, GSMEM_BYTES>>>();
    dim3 gi(16, 32, B_);
    k_inv<<<gi, 256>>>(out);
}

// round 13
// speedup vs baseline: 1.2749x; 1.0475x over previous
#include <cuda_runtime.h>
#include <cuda_fp16.h>
#include <cstdint>

// Problem constants
#define B_    16
#define CIN   256
#define COUT  256
#define EPS_F 1e-8f
#define NT    16384            // Winograd tiles total (16 b * 32 * 32)

// ================= scratch =================
__device__ float g_snorm;
__device__ float g_wsq[COUT*CIN];
__device__ float g_invwn[COUT];
__device__ float g_scale[B_*COUT];
// V: [tap 16][T 16384][ci 256] fp16 (134MB)
__device__ __align__(16) __half g_V[(size_t)16*NT*CIN];
// U: [tap 16][co 256][ci 256] fp16 (2MB)
__device__ __align__(16) __half g_U[16*COUT*CIN];
// M: [tap 16][co 256][T 16384] fp16 (134MB)
__device__ __align__(16) __half g_M[(size_t)16*COUT*NT];

// ================= helpers =================
__device__ __forceinline__ void mma_fp16(float& d0, float& d1, float& d2, float& d3,
                                         uint32_t a0, uint32_t a1, uint32_t a2, uint32_t a3,
                                         uint32_t b0, uint32_t b1) {
    asm volatile("mma.sync.aligned.m16n8k16.row.col.f32.f16.f16.f32 "
                 "{%0,%1,%2,%3}, {%4,%5,%6,%7}, {%8,%9}, {%0,%1,%2,%3};"
                 : "+f"(d0), "+f"(d1), "+f"(d2), "+f"(d3)
                 : "r"(a0), "r"(a1), "r"(a2), "r"(a3), "r"(b0), "r"(b1));
}
__device__ __forceinline__ void cp_async16(uint32_t saddr, const void* gaddr) {
    asm volatile("cp.async.cg.shared.global [%0], [%1], 16;"
                 :: "r"(saddr), "l"(gaddr) : "memory");
}
__device__ __forceinline__ void cp_commit() {
    asm volatile("cp.async.commit_group;" ::: "memory");
}
__device__ __forceinline__ void cp_wait1() {
    asm volatile("cp.async.wait_group 1;" ::: "memory");
}
__device__ __forceinline__ uint32_t smem_u32(const void* p) {
    uint32_t a;
    asm("{ .reg .u64 t; cvta.to.shared.u64 t, %1; cvt.u32.u64 %0, t; }"
        : "=r"(a) : "l"(p));
    return a;
}

// ================= norm/scale kernels =================
__global__ void k_snorm(const float* __restrict__ s) {
    __shared__ float red[256];
    float acc = 0.f;
    for (int i = threadIdx.x; i < B_*CIN; i += 256) { float v = s[i]; acc += v*v; }
    red[threadIdx.x] = acc; __syncthreads();
    for (int off = 128; off > 0; off >>= 1) {
        if (threadIdx.x < off) red[threadIdx.x] += red[threadIdx.x + off];
        __syncthreads();
    }
    if (threadIdx.x == 0) g_snorm = rsqrtf(red[0] / (float)(B_*CIN));
}

// merged: weight stats + Winograd weight transform (single w read)
__global__ void k_wprep(const float* __restrict__ w) {
    __shared__ float red[256];
    int co = blockIdx.x, ci = threadIdx.x;
    const float* gp = w + ((size_t)co*CIN + ci)*9;
    float g0[3], g1[3], g2[3];
#pragma unroll
    for (int c = 0; c < 3; ++c) { g0[c]=gp[c]; g1[c]=gp[3+c]; g2[c]=gp[6+c]; }
    float s9 = 0.f;
#pragma unroll
    for (int c = 0; c < 3; ++c) s9 += g0[c]*g0[c] + g1[c]*g1[c] + g2[c]*g2[c];
    g_wsq[co*CIN + ci] = s9;
    red[ci] = s9; __syncthreads();
    for (int off = 128; off > 0; off >>= 1) {
        if (ci < off) red[ci] += red[ci + off];
        __syncthreads();
    }
    if (ci == 0) g_invwn[co] = rsqrtf(red[0] / (float)(CIN*9));

    float tm[4][3];
#pragma unroll
    for (int c = 0; c < 3; ++c) {
        tm[0][c] = g0[c];
        tm[1][c] = 0.5f*(g0[c] + g1[c] + g2[c]);
        tm[2][c] = 0.5f*(g0[c] - g1[c] + g2[c]);
        tm[3][c] = g2[c];
    }
#pragma unroll
    for (int r = 0; r < 4; ++r) {
        float u0 = tm[r][0];
        float u1 = 0.5f*(tm[r][0] + tm[r][1] + tm[r][2]);
        float u2 = 0.5f*(tm[r][0] - tm[r][1] + tm[r][2]);
        float u3 = tm[r][2];
        g_U[(((size_t)((r*4+0)*COUT + co))<<8) + ci] = __float2half_rn(u0);
        g_U[(((size_t)((r*4+1)*COUT + co))<<8) + ci] = __float2half_rn(u1);
        g_U[(((size_t)((r*4+2)*COUT + co))<<8) + ci] = __float2half_rn(u2);
        g_U[(((size_t)((r*4+3)*COUT + co))<<8) + ci] = __float2half_rn(u3);
    }
}

__global__ void k_scale(const float* __restrict__ s) {
    __shared__ float red[256];
    int co = blockIdx.x, b = blockIdx.y, ci = threadIdx.x;
    float sn = s[b*CIN + ci] * g_snorm;
    red[ci] = sn*sn * g_wsq[co*CIN + ci]; __syncthreads();
    for (int off = 128; off > 0; off >>= 1) {
        if (ci < off) red[ci] += red[ci + off];
        __syncthreads();
    }
    if (ci == 0) {
        float iw = g_invwn[co];
        g_scale[b*COUT + co] = iw * rsqrtf(iw*iw*red[0] + EPS_F);
    }
}

// ================= input transform: V = B^T (x*s*snorm) B =================
// v3: 64-ci blocks, smem [r 4][col 66][ci 66pad] (ci fastest), ci-pair lanes.
// grid (32 ty, 4 ciT, 16 b), 256 threads, 69.7KB dyn smem (3 CTA/SM).
#define XCI 66                 // ci stride (64 + 2 pad)
#define XS3_BYTES (4*66*XCI*4) // 69696
__global__ __launch_bounds__(256)
void k_wino_x(const float* __restrict__ x, const float* __restrict__ s) {
    extern __shared__ float smx[];  // ((r*66 + col)*XCI + ci)
    const int tid  = threadIdx.x;
    const int lane = tid & 31;
    const int warp = tid >> 5;
    const int ty = blockIdx.x, ciT = blockIdx.y, b = blockIdx.z;
    const float snorm = g_snorm;
    const int r0 = 2*ty - 1;

    // ---- load: warp covers (8 ci x 4 c4-lanes); 16 iters = (r 4)(cq 4) ----
    {
        const int ciL = lane >> 2;          // 0..7
        const int c4l = lane & 3;           // 0..3
        const int ci  = warp*8 + ciL;       // 0..63
        const int gci = ciT*64 + ci;
        const float m = s[b*CIN + gci] * snorm;
        const float* xrowb = x + (((size_t)(b*CIN + gci)) << 12);
#pragma unroll
        for (int it = 0; it < 16; ++it) {
            int r  = it >> 2;
            int cq = it & 3;
            int c0 = (cq*4 + c4l) * 4;      // x col 0..60 step 4
            int gr = r0 + r;
            float4 v = make_float4(0.f, 0.f, 0.f, 0.f);
            if ((unsigned)gr < 64u)
                v = *(const float4*)(xrowb + gr*64 + c0);
            float* d = &smx[((r*66) + (c0 + 1))*XCI + ci];
            d[0*XCI] = v.x*m; d[1*XCI] = v.y*m;
            d[2*XCI] = v.z*m; d[3*XCI] = v.w*m;
        }
        // halo cols 0 (x=-1) and 65 (x=64): zero. 4r x 2 x 64ci = 512 -> 2/thr
#pragma unroll
        for (int it = 0; it < 2; ++it) {
            int lin = it*256 + tid;          // (r 4)(side 2)(ci 64)
            int cih = lin & 63;
            int side = (lin >> 6) & 1;
            int r = lin >> 7;
            smx[((r*66) + side*65)*XCI + cih] = 0.f;
        }
    }
    __syncthreads();

    // ---- transform: warp = txq, lane = ci pair (2*lane, 2*lane+1) ----
    const int ci0 = 2*lane;
#pragma unroll
    for (int k = 0; k < 4; ++k) {
        int tx = warp + 8*k;
        float2 d[4][4];
#pragma unroll
        for (int r = 0; r < 4; ++r)
#pragma unroll
            for (int c = 0; c < 4; ++c)
                d[r][c] = *(const float2*)&smx[((r*66) + (2*tx + c))*XCI + ci0];
        float2 m0[4], m1[4], m2[4], m3[4];
#pragma unroll
        for (int j = 0; j < 4; ++j) {
            m0[j].x = d[0][j].x - d[2][j].x;  m0[j].y = d[0][j].y - d[2][j].y;
            m1[j].x = d[1][j].x + d[2][j].x;  m1[j].y = d[1][j].y + d[2][j].y;
            m2[j].x = d[2][j].x - d[1][j].x;  m2[j].y = d[2][j].y - d[1][j].y;
            m3[j].x = d[1][j].x - d[3][j].x;  m3[j].y = d[1][j].y - d[3][j].y;
        }
        int T = b*1024 + ty*32 + tx;
        __half* vb = g_V + (((size_t)T) << 8) + ciT*64 + ci0;
#pragma unroll
        for (int r = 0; r < 4; ++r) {
            const float2* mr = (r==0)?m0:(r==1)?m1:(r==2)?m2:m3;
            float2 V0, V1, V2, V3;
            V0.x = mr[0].x - mr[2].x;  V0.y = mr[0].y - mr[2].y;
            V1.x = mr[1].x + mr[2].x;  V1.y = mr[1].y + mr[2].y;
            V2.x = mr[2].x - mr[1].x;  V2.y = mr[2].y - mr[1].y;
            V3.x = mr[1].x - mr[3].x;  V3.y = mr[1].y - mr[3].y;
            *(__half2*)(vb + ((size_t)(r*4+0)*NT << 8)) = __floats2half2_rn(V0.x, V0.y);
            *(__half2*)(vb + ((size_t)(r*4+1)*NT << 8)) = __floats2half2_rn(V1.x, V1.y);
            *(__half2*)(vb + ((size_t)(r*4+2)*NT << 8)) = __floats2half2_rn(V2.x, V2.y);
            *(__half2*)(vb + ((size_t)(r*4+3)*NT << 8)) = __floats2half2_rn(V3.x, V3.y);
        }
    }
}

// ================= kernel A: batched GEMM  M[tap] = U[tap] x V[tap] ====
// CTA 128co x 128T, warp m32 x n64 (8 warps: wm=wid&3, wn=wid>>2).
// K=256 in 4 phases of 64. 3-stage cp.async, wait_group 1, 2 CTA/SM.
#define KSTR 72
#define AT_HALFS (128*KSTR)                      // 9216
#define STG_HALFS (2*AT_HALFS)                   // 18432
#define GSMEM_BYTES (3*STG_HALFS*2)              // 110592
#define MSTR 136

__global__ __launch_bounds__(256, 2)
void k_gemm() {
    extern __shared__ __half smem[];
    const uint32_t smem_base = smem_u32(smem);

    const int t    = threadIdx.x;
    const int lane = t & 31;
    const int wm   = (t >> 5) & 3;        // m32 block
    const int wn   = t >> 7;              // n64 block
    const int g    = lane >> 2;
    const int t4   = lane & 3;

    const int coT   = blockIdx.x;         // 0..1 (fastest: shares V slab in L2)
    const int Tbase = blockIdx.y * 128;
    const int tap   = blockIdx.z;

    float c[2][8][4];
#pragma unroll
    for (int mb = 0; mb < 2; ++mb)
#pragma unroll
        for (int nb = 0; nb < 8; ++nb)
#pragma unroll
            for (int q = 0; q < 4; ++q) c[mb][nb][q] = 0.f;

    // phase = 64 k-columns. A: 128 rows x 8 uint4; B: 128 rows x 8 uint4.
    auto load_phase = [&](int p, int j) {
        uint32_t sbase = smem_base + (j*STG_HALFS)*2;
#pragma unroll
        for (int k4 = 0; k4 < 4; ++k4) {
            int lin = k4*256 + t;
            int row = lin >> 3, q = lin & 7;
            const __half* src = g_U + (((size_t)(tap*COUT + coT*128 + row)) << 8)
                              + p*64 + q*8;
            cp_async16(sbase + (row*KSTR + q*8)*2, src);
        }
#pragma unroll
        for (int k4 = 0; k4 < 4; ++k4) {
            int lin = k4*256 + t;
            int row = lin >> 3, q = lin & 7;
            const __half* src = g_V + (((size_t)(tap*NT + Tbase + row)) << 8)
                              + p*64 + q*8;
            cp_async16(sbase + (AT_HALFS + row*KSTR + q*8)*2, src);
        }
    };

    load_phase(0, 0); cp_commit();
    load_phase(1, 1); cp_commit();

    for (int p = 0; p < 4; ++p) {
        const int j = p % 3;
        cp_wait1();
        __syncthreads();
        if (p + 2 < 4) load_phase(p + 2, (p + 2) % 3);
        cp_commit();

        const __half* A  = smem + j*STG_HALFS;
        const __half* Bm = A + AT_HALFS;
#pragma unroll
        for (int ks = 0; ks < 4; ++ks) {
            uint32_t a[2][4];
#pragma unroll
            for (int mb = 0; mb < 2; ++mb) {
                const __half* ap = A + (wm*32 + mb*16 + g)*KSTR + ks*16 + 2*t4;
                a[mb][0] = *(const uint32_t*)(ap);
                a[mb][1] = *(const uint32_t*)(ap + 8*KSTR);
                a[mb][2] = *(const uint32_t*)(ap + 8);
                a[mb][3] = *(const uint32_t*)(ap + 8*KSTR + 8);
            }
            uint32_t bf[8][2];
#pragma unroll
            for (int nb = 0; nb < 8; ++nb) {
                const __half* bp = Bm + (wn*64 + nb*8 + g)*KSTR + ks*16 + 2*t4;
                bf[nb][0] = *(const uint32_t*)(bp);
                bf[nb][1] = *(const uint32_t*)(bp + 8);
            }
#pragma unroll
            for (int mb = 0; mb < 2; ++mb)
#pragma unroll
                for (int nb = 0; nb < 8; ++nb)
                    mma_fp16(c[mb][nb][0], c[mb][nb][1], c[mb][nb][2], c[mb][nb][3],
                             a[mb][0], a[mb][1], a[mb][2], a[mb][3],
                             bf[nb][0], bf[nb][1]);
        }
    }
    __syncthreads();

    // ---- epilogue: stage fp16 M tile in smem, then coalesced store ----
    __half* sM = smem;   // [128 co][MSTR]
#pragma unroll
    for (int mb = 0; mb < 2; ++mb) {
        int r0 = wm*32 + mb*16 + g;
        int col = wn*64 + 2*t4;
#pragma unroll
        for (int nb = 0; nb < 8; ++nb) {
            __half2 h01 = __floats2half2_rn(c[mb][nb][0], c[mb][nb][1]);
            __half2 h23 = __floats2half2_rn(c[mb][nb][2], c[mb][nb][3]);
            *(__half2*)(sM + r0*MSTR + col + nb*8) = h01;
            *(__half2*)(sM + (r0+8)*MSTR + col + nb*8) = h23;
        }
    }
    __syncthreads();
#pragma unroll
    for (int it = 0; it < 8; ++it) {
        int lin = it*256 + t;
        int row = lin >> 4, q = lin & 15;
        uint4 v = *(const uint4*)(sM + row*MSTR + q*8);
        *(uint4*)(g_M + ((size_t)(tap*COUT + coT*128 + row))*NT
                        + Tbase + q*8) = v;
    }
}

// ================= kernel B: inverse transform + demod scale ==========
// grid (16 tG, 32 coG, 16 b), 256 thr; warp=co, lane handles 2 tiles (half2)
__global__ __launch_bounds__(256)
void k_inv(float* __restrict__ out) {
    const int lane = threadIdx.x & 31;
    const int wid  = threadIdx.x >> 5;
    const int tG   = blockIdx.x;
    const int co   = blockIdx.y*8 + wid;
    const int b    = blockIdx.z;
    const int T    = b*1024 + tG*64 + lane*2;

    float2 m[16];
#pragma unroll
    for (int tap = 0; tap < 16; ++tap) {
        __half2 h = *(const __half2*)(g_M + ((size_t)(tap*COUT + co))*NT + T);
        m[tap] = __half22float2(h);
    }

    float sc = g_scale[b*COUT + co];
    int rel = (tG*64 + lane*2) & 1023;
    int tyy = rel >> 5, txx = rel & 31;       // txx even
    float* ob = out + (((size_t)(b*COUT + co)) << 12) + (2*tyy)*64 + 2*txx;

    float4 row0, row1;
    {   // element 0
        float t0[4], t1[4];
#pragma unroll
        for (int cc = 0; cc < 4; ++cc) {
            t0[cc] = m[cc].x + m[4+cc].x + m[8+cc].x;
            t1[cc] = m[4+cc].x - m[8+cc].x - m[12+cc].x;
        }
        row0.x = sc*(t0[0] + t0[1] + t0[2]);
        row0.y = sc*(t0[1] - t0[2] - t0[3]);
        row1.x = sc*(t1[0] + t1[1] + t1[2]);
        row1.y = sc*(t1[1] - t1[2] - t1[3]);
    }
    {   // element 1
        float t0[4], t1[4];
#pragma unroll
        for (int cc = 0; cc < 4; ++cc) {
            t0[cc] = m[cc].y + m[4+cc].y + m[8+cc].y;
            t1[cc] = m[4+cc].y - m[8+cc].y - m[12+cc].y;
        }
        row0.z = sc*(t0[0] + t0[1] + t0[2]);
        row0.w = sc*(t0[1] - t0[2] - t0[3]);
        row1.z = sc*(t1[0] + t1[1] + t1[2]);
        row1.w = sc*(t1[1] - t1[2] - t1[3]);
    }
    *(float4*)(ob)      = row0;
    *(float4*)(ob + 64) = row1;
}

// ================= launcher =================
extern "C" void kernel_launch(void* const* d_in, const int* in_sizes, int n_in,
                              void* d_out, int out_size) {
    const float* x = (const float*)d_in[0];   // [B, CIN, 64, 64]
    const float* s = (const float*)d_in[1];   // [B, CIN]
    const float* w = (const float*)d_in[2];   // [COUT, CIN, 3, 3]
    float* out = (float*)d_out;               // [B, COUT, 64, 64]

    cudaFuncSetAttribute(k_gemm, cudaFuncAttributeMaxDynamicSharedMemorySize,
                         GSMEM_BYTES);
    cudaFuncSetAttribute(k_wino_x, cudaFuncAttributeMaxDynamicSharedMemorySize,
                         XS3_BYTES);

    k_snorm<<<1, 256>>>(s);
    k_wprep<<<COUT, 256>>>(w);
    dim3 gs(COUT, B_);
    k_scale<<<gs, 256>>>(s);
    dim3 gx(32, 4, B_);
    k_wino_x<<<gx, 256, XS3_BYTES>>>(x, s);
    dim3 gg(2, 128, 16);
    k_gemm<<<gg, 256, GSMEM_BYTES>>>();
    dim3 gi(16, 32, B_);
    k_inv<<<gi, 256>>>(out);
}